// round 14
// baseline (speedup 1.0000x reference)
#include <cuda_runtime.h>
#include <cuda_fp16.h>
#include <mma.h>
#include <math.h>
#include <stdint.h>

using namespace nvcuda;

// ---------------- constants ----------------
#define Hd   1024
#define BATCH 8
#define SEQ  2048
#define MTOK (BATCH*SEQ)        // 16384
#define NENT 1000
#define TOPK 5
#define LNEPS 1e-5f
#define NEG_INF -3.4e38f

// output layout (floats), concatenated in reference return order
#define EF_OFF  0                         // entity_features  [8,2048,1024]
#define RF_OFF  (EF_OFF + MTOK*Hd)        // relation_features [8,1024]
#define RET_OFF (RF_OFF + BATCH*Hd)       // retrieved_entities [8,5,1024]
#define SIM_OFF (RET_OFF + BATCH*TOPK*Hd) // entity_similarities [8,1000]
#define IDX_OFF (SIM_OFF + BATCH*NENT)    // top_indices [8,5] (as float)
#define RO_OFF  (IDX_OFF + BATCH*TOPK)    // reasoning_output [8,1024]
#define VS_OFF  (RO_OFF + BATCH*Hd)       // validation_scores [8,1]

// ---------------- scratch (static device memory; no allocations) ----------------
__device__ __align__(128) __half g_ah[(size_t)MTOK * Hd];
__device__ __align__(128) __half g_mh[(size_t)MTOK * 2*Hd];
__device__ __align__(128) __half g_wt1[2*Hd * Hd];   // ee_w1^T fp16 [2048][1024]
__device__ __align__(128) __half g_wt2[Hd * 2*Hd];   // ee_w2^T fp16 [1024][2048]

#define PSEG 64
__device__ float g_pool_part[PSEG * BATCH*Hd];
__device__ float g_pooled[BATCH*Hd];
__device__ float g_part[8 * 8 * 2048];
__device__ float g_rmid[BATCH*Hd];
__device__ float g_rraw[BATCH*Hd];
__device__ float g_rin[BATCH*3*Hd];
__device__ float g_rmid2[BATCH*2*Hd];
__device__ float g_vmid[BATCH*512];
__device__ int   g_topidx[BATCH*TOPK];

// ---------------- math helpers ----------------
__device__ __forceinline__ float gelu_erf(float x) {
    return 0.5f * x * (1.0f + erff(x * 0.70710678118654752f));
}
__device__ __forceinline__ float sigmoidf_(float x) {
    return 1.0f / (1.0f + expf(-x));
}
__device__ __forceinline__ float apply_act(float v, int act) {
    if (act == 1) return gelu_erf(v);
    if (act == 2) return sigmoidf_(v);
    return v;
}

// ---------------- conversions ----------------
__global__ __launch_bounds__(256) void convert_h16(
    const float* __restrict__ x, __half* __restrict__ h, int n4)
{
    int i = blockIdx.x * 256 + threadIdx.x;
    if (i >= n4) return;
    float4 v = ((const float4*)x)[i];
    __half2* H = (__half2*)(h + 4*(size_t)i);
    H[0] = __half2(__float2half_rn(v.x), __float2half_rn(v.y));
    H[1] = __half2(__float2half_rn(v.z), __float2half_rn(v.w));
}

// W[K][N] fp32 -> WT fp16 [N][K]
__global__ __launch_bounds__(256) void transpose_h16(
    const float* __restrict__ W, __half* __restrict__ th, int K, int N)
{
    __shared__ float t[32][33];
    int n0 = blockIdx.x * 32, k0 = blockIdx.y * 32;
    int tx = threadIdx.x & 31, ty = threadIdx.x >> 5;   // 32x8
#pragma unroll
    for (int r = 0; r < 32; r += 8)
        t[ty + r][tx] = W[(size_t)(k0 + ty + r) * N + n0 + tx];
    __syncthreads();
#pragma unroll
    for (int r = 0; r < 32; r += 8)
        th[(size_t)(n0 + ty + r) * K + k0 + tx] = __float2half_rn(t[tx][ty + r]);
}

// ---------------- WMMA fp16 GEMM (128x128 block, 32x64 warp tiles) --------------
// C[M][N] = act(A @ B^T + bias), A [M][K] fp16, B rows [N][K] fp16, fp32 accum.
// mode 0: write fp32 C.  mode 1: gelu -> fp16 C.
#define BKC 32
#define LDK 40                               // fp16 leading dim with pad (80B row)
#define TILEB (128 * LDK * 2)                // 10240 B per operand tile
#define STAGEB (2 * TILEB)                   // Ah, Bh = 20480 B
#define GSMEM 40960                          // max(2*STAGEB, 64*LDC*4=33792)
#define LDC 132

__device__ __forceinline__ void cpa16(void* s, const void* g) {
    uint32_t sa;
    asm("{ .reg .u64 tmp; cvta.to.shared.u64 tmp, %1; cvt.u32.u64 %0, tmp; }"
        : "=r"(sa) : "l"(s));
    asm volatile("cp.async.cg.shared.global [%0], [%1], 16;" :: "r"(sa), "l"(g) : "memory");
}

// 128 rows x 32 fp16 (64B = 4 x 16B chunks per row), 512 chunks over 256 threads
template<int K>
__device__ __forceinline__ void load_tile_async(
    const __half* __restrict__ g, int row0, int kc, char* s, int tid)
{
    int r = tid >> 2, c = tid & 3;
#pragma unroll
    for (int h = 0; h < 2; h++) {
        int row = r + h * 64;
        cpa16(s + row * (LDK * 2) + c * 16,
              g + (size_t)(row0 + row) * K + kc + c * 8);
    }
}

template<int K>
__device__ __forceinline__ void stage_loads(
    const __half* ah, const __half* bh,
    int bm, int bn, int kc, char* st, int tid)
{
    load_tile_async<K>(ah, bm, kc, st + 0*TILEB, tid);
    load_tile_async<K>(bh, bn, kc, st + 1*TILEB, tid);
    asm volatile("cp.async.commit_group;" ::: "memory");
}

template<int K, int N>
__global__ __launch_bounds__(256) void gemm_tc(
    const __half* __restrict__ ah_g, const __half* __restrict__ bh_g,
    const float* __restrict__ bias,
    float* __restrict__ Cf, __half* __restrict__ ch_out,
    int mode)
{
    extern __shared__ char sm_[];
    const int tid = threadIdx.x;
    const int wid = tid >> 5;
    const int wm = wid & 3;          // 4 warps along M (32 rows each)
    const int wn = wid >> 2;         // 2 warps along N (64 cols each)
    const int bn = blockIdx.x * 128;
    const int bm = blockIdx.y * 128;

    wmma::fragment<wmma::accumulator, 16, 16, 16, float> acc[2][4];
#pragma unroll
    for (int mi = 0; mi < 2; mi++)
#pragma unroll
        for (int ni = 0; ni < 4; ni++) wmma::fill_fragment(acc[mi][ni], 0.0f);

    constexpr int NCH = K / BKC;

    stage_loads<K>(ah_g, bh_g, bm, bn, 0, sm_, tid);

    for (int ch = 0; ch < NCH; ch++) {
        if (ch + 1 < NCH) {
            stage_loads<K>(ah_g, bh_g, bm, bn, (ch + 1) * BKC,
                           sm_ + ((ch + 1) & 1) * STAGEB, tid);
            asm volatile("cp.async.wait_group 1;" ::: "memory");
        } else {
            asm volatile("cp.async.wait_group 0;" ::: "memory");
        }
        __syncthreads();

        char* st = sm_ + (ch & 1) * STAGEB;
        const __half* Ah = (const __half*)(st + 0*TILEB);
        const __half* Bh = (const __half*)(st + 1*TILEB);

#pragma unroll
        for (int kk = 0; kk < BKC; kk += 16) {
            wmma::fragment<wmma::matrix_a, 16, 16, 16, __half, wmma::row_major> af[2];
            wmma::fragment<wmma::matrix_b, 16, 16, 16, __half, wmma::col_major> bf[4];
#pragma unroll
            for (int mi = 0; mi < 2; mi++)
                wmma::load_matrix_sync(af[mi], Ah + (wm * 32 + mi * 16) * LDK + kk, LDK);
#pragma unroll
            for (int ni = 0; ni < 4; ni++)
                wmma::load_matrix_sync(bf[ni], Bh + (wn * 64 + ni * 16) * LDK + kk, LDK);
#pragma unroll
            for (int mi = 0; mi < 2; mi++)
#pragma unroll
                for (int ni = 0; ni < 4; ni++)
                    wmma::mma_sync(acc[mi][ni], af[mi], bf[ni], acc[mi][ni]);
        }
        __syncthreads();
    }

    // ---- epilogue in two 64-row slabs (reuses mainloop SMEM) ----
    float* Cs = (float*)sm_;                 // 64 x LDC fp32 = 33792 B
#pragma unroll
    for (int mi = 0; mi < 2; mi++) {
#pragma unroll
        for (int ni = 0; ni < 4; ni++)
            wmma::store_matrix_sync(Cs + (wm * 16) * LDC + wn * 64 + ni * 16,
                                    acc[mi][ni], LDC, wmma::mem_row_major);
        __syncthreads();

        for (int i = tid; i < 64 * 32; i += 256) {
            int srow = i >> 5;
            int col = (i & 31) * 4;
            int grow = bm + (srow >> 4) * 32 + mi * 16 + (srow & 15);
            float4 v = *(float4*)&Cs[srow * LDC + col];
            v.x += bias[bn + col + 0];
            v.y += bias[bn + col + 1];
            v.z += bias[bn + col + 2];
            v.w += bias[bn + col + 3];
            size_t o = (size_t)grow * N + bn + col;
            if (mode == 0) {
                *(float4*)&Cf[o] = v;
            } else {
                __half2* H = (__half2*)(ch_out + o);
                H[0] = __half2(__float2half_rn(gelu_erf(v.x)),
                               __float2half_rn(gelu_erf(v.y)));
                H[1] = __half2(__float2half_rn(gelu_erf(v.z)),
                               __float2half_rn(gelu_erf(v.w)));
            }
        }
        __syncthreads();
    }
}

// ---------------- per-row LayerNorm over H=1024 (in-place safe) ----------------
__global__ __launch_bounds__(256) void ln_rows(
    const float* __restrict__ X, const float* __restrict__ g,
    const float* __restrict__ beta, float* __restrict__ Y)
{
    const int row = blockIdx.x;
    const int tid = threadIdx.x;
    const float* x = X + (size_t)row * Hd;
    float v[4];
    float s = 0.0f, q = 0.0f;
#pragma unroll
    for (int i = 0; i < 4; i++) {
        v[i] = x[tid + i * 256];
        s += v[i];
        q += v[i] * v[i];
    }
    __shared__ float sh1[256], sh2[256];
    sh1[tid] = s; sh2[tid] = q;
    __syncthreads();
    for (int o = 128; o; o >>= 1) {
        if (tid < o) { sh1[tid] += sh1[tid + o]; sh2[tid] += sh2[tid + o]; }
        __syncthreads();
    }
    float mu = sh1[0] * (1.0f / Hd);
    float var = sh2[0] * (1.0f / Hd) - mu * mu;
    float inv = rsqrtf(var + LNEPS);
    float* y = Y + (size_t)row * Hd;
#pragma unroll
    for (int i = 0; i < 4; i++) {
        int c = tid + i * 256;
        y[c] = (v[i] - mu) * inv * g[c] + beta[c];
    }
}

// ---------------- mean pool over sequence ----------------
__global__ void pool_partial(const float* __restrict__ hid)
{
    int idx = blockIdx.x * 256 + threadIdx.x;   // 0..8191
    int ss = blockIdx.y;                        // 0..PSEG-1
    int b = idx >> 10, h = idx & 1023;
    float s = 0.0f;
    int s0 = ss * (SEQ / PSEG);
    const float* base = hid + ((size_t)b * SEQ + s0) * Hd + h;
#pragma unroll 4
    for (int t = 0; t < SEQ / PSEG; t++) s += base[(size_t)t * Hd];
    g_pool_part[ss * (BATCH * Hd) + idx] = s;
}
__global__ void pool_combine()
{
    int idx = blockIdx.x * 256 + threadIdx.x;
    float s = 0.0f;
#pragma unroll
    for (int ss = 0; ss < PSEG; ss++) s += g_pool_part[ss * (BATCH * Hd) + idx];
    g_pooled[idx] = s * (1.0f / SEQ);
}

// ---------------- small GEMM (8 rows) with deterministic K-split ----------------
#define KSPLIT 8
__global__ void sg_partial(const float* __restrict__ X, const float* __restrict__ W,
                           int K, int N)
{
    int n = blockIdx.x * blockDim.x + threadIdx.x;
    int ks = blockIdx.y;
    if (n >= N) return;
    int kchunk = K / KSPLIT;
    int k0 = ks * kchunk, k1 = k0 + kchunk;
    float acc[8];
#pragma unroll
    for (int r = 0; r < 8; r++) acc[r] = 0.0f;
    for (int k = k0; k < k1; k++) {
        float w = W[(size_t)k * N + n];
#pragma unroll
        for (int r = 0; r < 8; r++) acc[r] = fmaf(__ldg(&X[r * K + k]), w, acc[r]);
    }
#pragma unroll
    for (int r = 0; r < 8; r++) g_part[(ks * 8 + r) * N + n] = acc[r];
}
__global__ void sg_combine(const float* __restrict__ bias, float* __restrict__ Y,
                           int N, int act)
{
    int i = blockIdx.x * blockDim.x + threadIdx.x;
    if (i >= 8 * N) return;
    int r = i / N, n = i - r * N;
    float s = bias[n];
#pragma unroll
    for (int ks = 0; ks < KSPLIT; ks++) s += g_part[(ks * 8 + r) * N + n];
    Y[i] = apply_act(s, act);
}

// ---------------- entity similarities ----------------
__global__ __launch_bounds__(128) void sims_kernel(
    const float* __restrict__ E, const float* __restrict__ relf,
    float* __restrict__ sims)
{
    int n = blockIdx.x;
    int tid = threadIdx.x;
    __shared__ float rs[BATCH * Hd];
    for (int i = tid; i < BATCH * Hd; i += 128) rs[i] = relf[i];
    __syncthreads();
    float acc[8];
#pragma unroll
    for (int r = 0; r < 8; r++) acc[r] = 0.0f;
    for (int k = tid; k < Hd; k += 128) {
        float e = E[(size_t)n * Hd + k];
#pragma unroll
        for (int r = 0; r < 8; r++) acc[r] = fmaf(e, rs[r * Hd + k], acc[r]);
    }
    __shared__ float red[8][128];
#pragma unroll
    for (int r = 0; r < 8; r++) red[r][tid] = acc[r];
    __syncthreads();
    for (int o = 64; o; o >>= 1) {
        if (tid < o) {
#pragma unroll
            for (int r = 0; r < 8; r++) red[r][tid] += red[r][tid + o];
        }
        __syncthreads();
    }
    if (tid < 8) sims[tid * NENT + n] = red[tid][0];
}

// ---------------- top-5 (desc, lowest index on ties) ----------------
__global__ __launch_bounds__(256) void topk_kernel(const float* __restrict__ sims,
                                                   float* __restrict__ fidx_out)
{
    int b = blockIdx.x;
    int tid = threadIdx.x;
    __shared__ float sv[1024];
    for (int i = tid; i < 1024; i += 256)
        sv[i] = (i < NENT) ? sims[b * NENT + i] : NEG_INF;
    __syncthreads();
    __shared__ float bv[256];
    __shared__ int bi[256];
    for (int t = 0; t < TOPK; t++) {
        float best = NEG_INF; int besti = 0;
        for (int i = tid; i < NENT; i += 256) {
            float vv = sv[i];
            if (vv > best) { best = vv; besti = i; }
        }
        bv[tid] = best; bi[tid] = besti;
        __syncthreads();
        for (int o = 128; o; o >>= 1) {
            if (tid < o) {
                if (bv[tid + o] > bv[tid] ||
                    (bv[tid + o] == bv[tid] && bi[tid + o] < bi[tid])) {
                    bv[tid] = bv[tid + o]; bi[tid] = bi[tid + o];
                }
            }
            __syncthreads();
        }
        if (tid == 0) {
            g_topidx[b * TOPK + t] = bi[0];
            fidx_out[b * TOPK + t] = (float)bi[0];
            sv[bi[0]] = NEG_INF;
        }
        __syncthreads();
    }
}

// ---------------- gather retrieved entities + build reasoning input ----------------
__global__ __launch_bounds__(256) void build_rin(
    const float* __restrict__ E, const float* __restrict__ relf,
    float* __restrict__ ret_out)
{
    int b = blockIdx.x;
    for (int h = threadIdx.x; h < Hd; h += 256) {
        float s = 0.0f;
#pragma unroll
        for (int k = 0; k < TOPK; k++) {
            float v = E[(size_t)g_topidx[b * TOPK + k] * Hd + h];
            ret_out[((size_t)b * TOPK + k) * Hd + h] = v;
            s += v;
        }
        g_rin[b * 3 * Hd + h]          = s * (1.0f / TOPK);
        g_rin[b * 3 * Hd + Hd + h]     = relf[b * Hd + h];
        g_rin[b * 3 * Hd + 2 * Hd + h] = g_pooled[b * Hd + h];
    }
}

// ---------------- launch ----------------
extern "C" void kernel_launch(void* const* d_in, const int* in_sizes, int n_in,
                              void* d_out, int out_size)
{
    const float* hid    = (const float*)d_in[0];
    const float* ent    = (const float*)d_in[1];
    const float* ee_w1  = (const float*)d_in[2];
    const float* ee_b1  = (const float*)d_in[3];
    const float* ee_w2  = (const float*)d_in[4];
    const float* ee_b2  = (const float*)d_in[5];
    const float* ee_g   = (const float*)d_in[6];
    const float* ee_be  = (const float*)d_in[7];
    const float* re_w1  = (const float*)d_in[8];
    const float* re_b1  = (const float*)d_in[9];
    const float* re_w2  = (const float*)d_in[10];
    const float* re_b2  = (const float*)d_in[11];
    const float* re_g   = (const float*)d_in[12];
    const float* re_be  = (const float*)d_in[13];
    const float* rn_w1  = (const float*)d_in[14];
    const float* rn_b1  = (const float*)d_in[15];
    const float* rn_w2  = (const float*)d_in[16];
    const float* rn_b2  = (const float*)d_in[17];
    const float* rn_g   = (const float*)d_in[18];
    const float* rn_be  = (const float*)d_in[19];
    const float* vn_w1  = (const float*)d_in[20];
    const float* vn_b1  = (const float*)d_in[21];
    const float* vn_w2  = (const float*)d_in[22];
    const float* vn_b2  = (const float*)d_in[23];
    float* out = (float*)d_out;

    __half *ah, *mh, *wt1, *wt2;
    float *pooled, *rmid, *rraw, *rin, *rmid2, *vmid;
    cudaGetSymbolAddress((void**)&ah,  g_ah);
    cudaGetSymbolAddress((void**)&mh,  g_mh);
    cudaGetSymbolAddress((void**)&wt1, g_wt1);
    cudaGetSymbolAddress((void**)&wt2, g_wt2);
    cudaGetSymbolAddress((void**)&pooled, g_pooled);
    cudaGetSymbolAddress((void**)&rmid,   g_rmid);
    cudaGetSymbolAddress((void**)&rraw,   g_rraw);
    cudaGetSymbolAddress((void**)&rin,    g_rin);
    cudaGetSymbolAddress((void**)&rmid2,  g_rmid2);
    cudaGetSymbolAddress((void**)&vmid,   g_vmid);

    cudaFuncSetAttribute(gemm_tc<Hd, 2*Hd>,
                         cudaFuncAttributeMaxDynamicSharedMemorySize, GSMEM);
    cudaFuncSetAttribute(gemm_tc<2*Hd, Hd>,
                         cudaFuncAttributeMaxDynamicSharedMemorySize, GSMEM);

    // one-time host resources (no device memory involved)
    static cudaStream_t s2 = nullptr;
    static cudaEvent_t evFork = nullptr, evJoin = nullptr;
    if (!s2) {
        int loPri, hiPri;
        cudaDeviceGetStreamPriorityRange(&loPri, &hiPri);
        cudaStreamCreateWithPriority(&s2, cudaStreamNonBlocking, hiPri);
        cudaEventCreateWithFlags(&evFork, cudaEventDisableTiming);
        cudaEventCreateWithFlags(&evJoin, cudaEventDisableTiming);
    }

    // ---- fork: side stream joins the capture ----
    cudaEventRecord(evFork, 0);
    cudaStreamWaitEvent(s2, evFork, 0);

    // ================= Chain A (default stream): entity encoder =================
    convert_h16<<<(MTOK * Hd / 4 + 255) / 256, 256>>>(hid, ah, MTOK * Hd / 4);
    transpose_h16<<<dim3(2 * Hd / 32, Hd / 32), 256>>>(ee_w1, wt1, Hd, 2 * Hd);
    transpose_h16<<<dim3(Hd / 32, 2 * Hd / 32), 256>>>(ee_w2, wt2, 2 * Hd, Hd);
    gemm_tc<Hd, 2*Hd><<<dim3(2 * Hd / 128, MTOK / 128), 256, GSMEM>>>(
        ah, wt1, ee_b1, nullptr, mh, 1);
    gemm_tc<2*Hd, Hd><<<dim3(Hd / 128, MTOK / 128), 256, GSMEM>>>(
        mh, wt2, ee_b2, out + EF_OFF, nullptr, 0);
    ln_rows<<<MTOK, 256>>>(out + EF_OFF, ee_g, ee_be, out + EF_OFF);

    // ================= Chain B (stream s2, high priority): pooled path ==========
    pool_partial<<<dim3(32, PSEG), 256, 0, s2>>>(hid);
    pool_combine<<<32, 256, 0, s2>>>();

    sg_partial<<<dim3(Hd / 256, KSPLIT), 256, 0, s2>>>(pooled, re_w1, Hd, Hd);
    sg_combine<<<(8 * Hd + 255) / 256, 256, 0, s2>>>(re_b1, rmid, Hd, 1);
    sg_partial<<<dim3(Hd / 256, KSPLIT), 256, 0, s2>>>(rmid, re_w2, Hd, Hd);
    sg_combine<<<(8 * Hd + 255) / 256, 256, 0, s2>>>(re_b2, rraw, Hd, 0);
    ln_rows<<<BATCH, 256, 0, s2>>>(rraw, re_g, re_be, out + RF_OFF);

    sims_kernel<<<NENT, 128, 0, s2>>>(ent, out + RF_OFF, out + SIM_OFF);
    topk_kernel<<<BATCH, 256, 0, s2>>>(out + SIM_OFF, out + IDX_OFF);
    build_rin<<<BATCH, 256, 0, s2>>>(ent, out + RF_OFF, out + RET_OFF);

    sg_partial<<<dim3(2 * Hd / 256, KSPLIT), 256, 0, s2>>>(rin, rn_w1, 3 * Hd, 2 * Hd);
    sg_combine<<<(8 * 2 * Hd + 255) / 256, 256, 0, s2>>>(rn_b1, rmid2, 2 * Hd, 1);
    sg_partial<<<dim3(Hd / 256, KSPLIT), 256, 0, s2>>>(rmid2, rn_w2, 2 * Hd, Hd);
    sg_combine<<<(8 * Hd + 255) / 256, 256, 0, s2>>>(rn_b2, rraw, Hd, 0);
    ln_rows<<<BATCH, 256, 0, s2>>>(rraw, rn_g, rn_be, out + RO_OFF);

    sg_partial<<<dim3(512 / 256, KSPLIT), 256, 0, s2>>>(out + RO_OFF, vn_w1, Hd, 512);
    sg_combine<<<(8 * 512 + 255) / 256, 256, 0, s2>>>(vn_b1, vmid, 512, 1);
    sg_partial<<<dim3(1, KSPLIT), 256, 0, s2>>>(vmid, vn_w2, 512, 1);
    sg_combine<<<1, 256, 0, s2>>>(vn_b2, out + VS_OFF, 1, 2);

    // ---- join: default stream waits for Chain B ----
    cudaEventRecord(evJoin, s2);
    cudaStreamWaitEvent(0, evJoin, 0);
}

// round 15
// speedup vs baseline: 1.0401x; 1.0401x over previous
#include <cuda_runtime.h>
#include <cuda_fp16.h>
#include <mma.h>
#include <math.h>
#include <stdint.h>

using namespace nvcuda;

// ---------------- constants ----------------
#define Hd   1024
#define BATCH 8
#define SEQ  2048
#define MTOK (BATCH*SEQ)        // 16384
#define NENT 1000
#define TOPK 5
#define LNEPS 1e-5f
#define NEG_INF -3.4e38f

// output layout (floats), concatenated in reference return order
#define EF_OFF  0                         // entity_features  [8,2048,1024]
#define RF_OFF  (EF_OFF + MTOK*Hd)        // relation_features [8,1024]
#define RET_OFF (RF_OFF + BATCH*Hd)       // retrieved_entities [8,5,1024]
#define SIM_OFF (RET_OFF + BATCH*TOPK*Hd) // entity_similarities [8,1000]
#define IDX_OFF (SIM_OFF + BATCH*NENT)    // top_indices [8,5] (as float)
#define RO_OFF  (IDX_OFF + BATCH*TOPK)    // reasoning_output [8,1024]
#define VS_OFF  (RO_OFF + BATCH*Hd)       // validation_scores [8,1]

// ---------------- scratch (static device memory; no allocations) ----------------
__device__ __align__(128) __half g_ah[(size_t)MTOK * Hd];
__device__ __align__(128) __half g_mh[(size_t)MTOK * 2*Hd];
__device__ __align__(128) __half g_wt1[2*Hd * Hd];   // ee_w1^T fp16 [2048][1024]
__device__ __align__(128) __half g_wt2[Hd * 2*Hd];   // ee_w2^T fp16 [1024][2048]

#define PSEG 64
__device__ float g_pool_part[PSEG * BATCH*Hd];
__device__ float g_pooled[BATCH*Hd];
__device__ float g_part[8 * 8 * 2048];
__device__ float g_rmid[BATCH*Hd];
__device__ float g_rraw[BATCH*Hd];
__device__ float g_rin[BATCH*3*Hd];
__device__ float g_rmid2[BATCH*2*Hd];
__device__ float g_vmid[BATCH*512];
__device__ int   g_topidx[BATCH*TOPK];

// ---------------- math helpers ----------------
__device__ __forceinline__ float gelu_erf(float x) {
    return 0.5f * x * (1.0f + erff(x * 0.70710678118654752f));
}
__device__ __forceinline__ float sigmoidf_(float x) {
    return 1.0f / (1.0f + expf(-x));
}
__device__ __forceinline__ float apply_act(float v, int act) {
    if (act == 1) return gelu_erf(v);
    if (act == 2) return sigmoidf_(v);
    return v;
}

// ---------------- conversions ----------------
__global__ __launch_bounds__(256) void convert_h16(
    const float* __restrict__ x, __half* __restrict__ h, int n4)
{
    int i = blockIdx.x * 256 + threadIdx.x;
    if (i >= n4) return;
    float4 v = ((const float4*)x)[i];
    __half2* H = (__half2*)(h + 4*(size_t)i);
    H[0] = __half2(__float2half_rn(v.x), __float2half_rn(v.y));
    H[1] = __half2(__float2half_rn(v.z), __float2half_rn(v.w));
}

// W[K][N] fp32 -> WT fp16 [N][K]
__global__ __launch_bounds__(256) void transpose_h16(
    const float* __restrict__ W, __half* __restrict__ th, int K, int N)
{
    __shared__ float t[32][33];
    int n0 = blockIdx.x * 32, k0 = blockIdx.y * 32;
    int tx = threadIdx.x & 31, ty = threadIdx.x >> 5;   // 32x8
#pragma unroll
    for (int r = 0; r < 32; r += 8)
        t[ty + r][tx] = W[(size_t)(k0 + ty + r) * N + n0 + tx];
    __syncthreads();
#pragma unroll
    for (int r = 0; r < 32; r += 8)
        th[(size_t)(n0 + ty + r) * K + k0 + tx] = __float2half_rn(t[tx][ty + r]);
}

// ---------------- WMMA fp16 GEMM (128x128 block, 32x64 warp tiles) --------------
// C[M][N] = act(A @ B^T + bias), A [M][K] fp16, B rows [N][K] fp16, fp32 accum.
// row0: M offset of this launch's slab. mode 0: fp32 C. mode 1: gelu -> fp16 C.
#define BKC 32
#define LDK 40                               // fp16 leading dim with pad (80B row)
#define TILEB (128 * LDK * 2)                // 10240 B per operand tile
#define STAGEB (2 * TILEB)                   // Ah, Bh = 20480 B
#define GSMEM 40960                          // max(2*STAGEB, 64*LDC*4=33792)
#define LDC 132

__device__ __forceinline__ void cpa16(void* s, const void* g) {
    uint32_t sa;
    asm("{ .reg .u64 tmp; cvta.to.shared.u64 tmp, %1; cvt.u32.u64 %0, tmp; }"
        : "=r"(sa) : "l"(s));
    asm volatile("cp.async.cg.shared.global [%0], [%1], 16;" :: "r"(sa), "l"(g) : "memory");
}

template<int K>
__device__ __forceinline__ void load_tile_async(
    const __half* __restrict__ g, int row0, int kc, char* s, int tid)
{
    int r = tid >> 2, c = tid & 3;
#pragma unroll
    for (int h = 0; h < 2; h++) {
        int row = r + h * 64;
        cpa16(s + row * (LDK * 2) + c * 16,
              g + (size_t)(row0 + row) * K + kc + c * 8);
    }
}

template<int K>
__device__ __forceinline__ void stage_loads(
    const __half* ah, const __half* bh,
    int bm, int bn, int kc, char* st, int tid)
{
    load_tile_async<K>(ah, bm, kc, st + 0*TILEB, tid);
    load_tile_async<K>(bh, bn, kc, st + 1*TILEB, tid);
    asm volatile("cp.async.commit_group;" ::: "memory");
}

template<int K, int N>
__global__ __launch_bounds__(256) void gemm_tc(
    const __half* __restrict__ ah_g, const __half* __restrict__ bh_g,
    const float* __restrict__ bias,
    float* __restrict__ Cf, __half* __restrict__ ch_out,
    int row_off, int mode)
{
    extern __shared__ char sm_[];
    const int tid = threadIdx.x;
    const int wid = tid >> 5;
    const int wm = wid & 3;          // 4 warps along M (32 rows each)
    const int wn = wid >> 2;         // 2 warps along N (64 cols each)
    const int bn = blockIdx.x * 128;
    const int bm = row_off + blockIdx.y * 128;

    wmma::fragment<wmma::accumulator, 16, 16, 16, float> acc[2][4];
#pragma unroll
    for (int mi = 0; mi < 2; mi++)
#pragma unroll
        for (int ni = 0; ni < 4; ni++) wmma::fill_fragment(acc[mi][ni], 0.0f);

    constexpr int NCH = K / BKC;

    stage_loads<K>(ah_g, bh_g, bm, bn, 0, sm_, tid);

    for (int ch = 0; ch < NCH; ch++) {
        if (ch + 1 < NCH) {
            stage_loads<K>(ah_g, bh_g, bm, bn, (ch + 1) * BKC,
                           sm_ + ((ch + 1) & 1) * STAGEB, tid);
            asm volatile("cp.async.wait_group 1;" ::: "memory");
        } else {
            asm volatile("cp.async.wait_group 0;" ::: "memory");
        }
        __syncthreads();

        char* st = sm_ + (ch & 1) * STAGEB;
        const __half* Ah = (const __half*)(st + 0*TILEB);
        const __half* Bh = (const __half*)(st + 1*TILEB);

#pragma unroll
        for (int kk = 0; kk < BKC; kk += 16) {
            wmma::fragment<wmma::matrix_a, 16, 16, 16, __half, wmma::row_major> af[2];
            wmma::fragment<wmma::matrix_b, 16, 16, 16, __half, wmma::col_major> bf[4];
#pragma unroll
            for (int mi = 0; mi < 2; mi++)
                wmma::load_matrix_sync(af[mi], Ah + (wm * 32 + mi * 16) * LDK + kk, LDK);
#pragma unroll
            for (int ni = 0; ni < 4; ni++)
                wmma::load_matrix_sync(bf[ni], Bh + (wn * 64 + ni * 16) * LDK + kk, LDK);
#pragma unroll
            for (int mi = 0; mi < 2; mi++)
#pragma unroll
                for (int ni = 0; ni < 4; ni++)
                    wmma::mma_sync(acc[mi][ni], af[mi], bf[ni], acc[mi][ni]);
        }
        __syncthreads();
    }

    // ---- epilogue in two 64-row slabs (reuses mainloop SMEM) ----
    float* Cs = (float*)sm_;                 // 64 x LDC fp32 = 33792 B
#pragma unroll
    for (int mi = 0; mi < 2; mi++) {
#pragma unroll
        for (int ni = 0; ni < 4; ni++)
            wmma::store_matrix_sync(Cs + (wm * 16) * LDC + wn * 64 + ni * 16,
                                    acc[mi][ni], LDC, wmma::mem_row_major);
        __syncthreads();

        for (int i = tid; i < 64 * 32; i += 256) {
            int srow = i >> 5;
            int col = (i & 31) * 4;
            int grow = bm + (srow >> 4) * 32 + mi * 16 + (srow & 15);
            float4 v = *(float4*)&Cs[srow * LDC + col];
            v.x += bias[bn + col + 0];
            v.y += bias[bn + col + 1];
            v.z += bias[bn + col + 2];
            v.w += bias[bn + col + 3];
            size_t o = (size_t)grow * N + bn + col;
            if (mode == 0) {
                *(float4*)&Cf[o] = v;
            } else {
                __half2* H = (__half2*)(ch_out + o);
                H[0] = __half2(__float2half_rn(gelu_erf(v.x)),
                               __float2half_rn(gelu_erf(v.y)));
                H[1] = __half2(__float2half_rn(gelu_erf(v.z)),
                               __float2half_rn(gelu_erf(v.w)));
            }
        }
        __syncthreads();
    }
}

// ---------------- per-row LayerNorm over H=1024 (in-place safe) ----------------
__global__ __launch_bounds__(256) void ln_rows(
    const float* __restrict__ X, const float* __restrict__ g,
    const float* __restrict__ beta, float* __restrict__ Y)
{
    const int row = blockIdx.x;
    const int tid = threadIdx.x;
    const float* x = X + (size_t)row * Hd;
    float v[4];
    float s = 0.0f, q = 0.0f;
#pragma unroll
    for (int i = 0; i < 4; i++) {
        v[i] = x[tid + i * 256];
        s += v[i];
        q += v[i] * v[i];
    }
    __shared__ float sh1[256], sh2[256];
    sh1[tid] = s; sh2[tid] = q;
    __syncthreads();
    for (int o = 128; o; o >>= 1) {
        if (tid < o) { sh1[tid] += sh1[tid + o]; sh2[tid] += sh2[tid + o]; }
        __syncthreads();
    }
    float mu = sh1[0] * (1.0f / Hd);
    float var = sh2[0] * (1.0f / Hd) - mu * mu;
    float inv = rsqrtf(var + LNEPS);
    float* y = Y + (size_t)row * Hd;
#pragma unroll
    for (int i = 0; i < 4; i++) {
        int c = tid + i * 256;
        y[c] = (v[i] - mu) * inv * g[c] + beta[c];
    }
}

// ---------------- mean pool over sequence ----------------
__global__ void pool_partial(const float* __restrict__ hid)
{
    int idx = blockIdx.x * 256 + threadIdx.x;   // 0..8191
    int ss = blockIdx.y;                        // 0..PSEG-1
    int b = idx >> 10, h = idx & 1023;
    float s = 0.0f;
    int s0 = ss * (SEQ / PSEG);
    const float* base = hid + ((size_t)b * SEQ + s0) * Hd + h;
#pragma unroll 4
    for (int t = 0; t < SEQ / PSEG; t++) s += base[(size_t)t * Hd];
    g_pool_part[ss * (BATCH * Hd) + idx] = s;
}
__global__ void pool_combine()
{
    int idx = blockIdx.x * 256 + threadIdx.x;
    float s = 0.0f;
#pragma unroll
    for (int ss = 0; ss < PSEG; ss++) s += g_pool_part[ss * (BATCH * Hd) + idx];
    g_pooled[idx] = s * (1.0f / SEQ);
}

// ---------------- small GEMM (8 rows) with deterministic K-split ----------------
#define KSPLIT 8
__global__ void sg_partial(const float* __restrict__ X, const float* __restrict__ W,
                           int K, int N)
{
    int n = blockIdx.x * blockDim.x + threadIdx.x;
    int ks = blockIdx.y;
    if (n >= N) return;
    int kchunk = K / KSPLIT;
    int k0 = ks * kchunk, k1 = k0 + kchunk;
    float acc[8];
#pragma unroll
    for (int r = 0; r < 8; r++) acc[r] = 0.0f;
    for (int k = k0; k < k1; k++) {
        float w = W[(size_t)k * N + n];
#pragma unroll
        for (int r = 0; r < 8; r++) acc[r] = fmaf(__ldg(&X[r * K + k]), w, acc[r]);
    }
#pragma unroll
    for (int r = 0; r < 8; r++) g_part[(ks * 8 + r) * N + n] = acc[r];
}
__global__ void sg_combine(const float* __restrict__ bias, float* __restrict__ Y,
                           int N, int act)
{
    int i = blockIdx.x * blockDim.x + threadIdx.x;
    if (i >= 8 * N) return;
    int r = i / N, n = i - r * N;
    float s = bias[n];
#pragma unroll
    for (int ks = 0; ks < KSPLIT; ks++) s += g_part[(ks * 8 + r) * N + n];
    Y[i] = apply_act(s, act);
}

// ---------------- entity similarities ----------------
__global__ __launch_bounds__(128) void sims_kernel(
    const float* __restrict__ E, const float* __restrict__ relf,
    float* __restrict__ sims)
{
    int n = blockIdx.x;
    int tid = threadIdx.x;
    __shared__ float rs[BATCH * Hd];
    for (int i = tid; i < BATCH * Hd; i += 128) rs[i] = relf[i];
    __syncthreads();
    float acc[8];
#pragma unroll
    for (int r = 0; r < 8; r++) acc[r] = 0.0f;
    for (int k = tid; k < Hd; k += 128) {
        float e = E[(size_t)n * Hd + k];
#pragma unroll
        for (int r = 0; r < 8; r++) acc[r] = fmaf(e, rs[r * Hd + k], acc[r]);
    }
    __shared__ float red[8][128];
#pragma unroll
    for (int r = 0; r < 8; r++) red[r][tid] = acc[r];
    __syncthreads();
    for (int o = 64; o; o >>= 1) {
        if (tid < o) {
#pragma unroll
            for (int r = 0; r < 8; r++) red[r][tid] += red[r][tid + o];
        }
        __syncthreads();
    }
    if (tid < 8) sims[tid * NENT + n] = red[tid][0];
}

// ---------------- top-5 (desc, lowest index on ties) ----------------
__global__ __launch_bounds__(256) void topk_kernel(const float* __restrict__ sims,
                                                   float* __restrict__ fidx_out)
{
    int b = blockIdx.x;
    int tid = threadIdx.x;
    __shared__ float sv[1024];
    for (int i = tid; i < 1024; i += 256)
        sv[i] = (i < NENT) ? sims[b * NENT + i] : NEG_INF;
    __syncthreads();
    __shared__ float bv[256];
    __shared__ int bi[256];
    for (int t = 0; t < TOPK; t++) {
        float best = NEG_INF; int besti = 0;
        for (int i = tid; i < NENT; i += 256) {
            float vv = sv[i];
            if (vv > best) { best = vv; besti = i; }
        }
        bv[tid] = best; bi[tid] = besti;
        __syncthreads();
        for (int o = 128; o; o >>= 1) {
            if (tid < o) {
                if (bv[tid + o] > bv[tid] ||
                    (bv[tid + o] == bv[tid] && bi[tid + o] < bi[tid])) {
                    bv[tid] = bv[tid + o]; bi[tid] = bi[tid + o];
                }
            }
            __syncthreads();
        }
        if (tid == 0) {
            g_topidx[b * TOPK + t] = bi[0];
            fidx_out[b * TOPK + t] = (float)bi[0];
            sv[bi[0]] = NEG_INF;
        }
        __syncthreads();
    }
}

// ---------------- gather retrieved entities + build reasoning input ----------------
__global__ __launch_bounds__(256) void build_rin(
    const float* __restrict__ E, const float* __restrict__ relf,
    float* __restrict__ ret_out)
{
    int b = blockIdx.x;
    for (int h = threadIdx.x; h < Hd; h += 256) {
        float s = 0.0f;
#pragma unroll
        for (int k = 0; k < TOPK; k++) {
            float v = E[(size_t)g_topidx[b * TOPK + k] * Hd + h];
            ret_out[((size_t)b * TOPK + k) * Hd + h] = v;
            s += v;
        }
        g_rin[b * 3 * Hd + h]          = s * (1.0f / TOPK);
        g_rin[b * 3 * Hd + Hd + h]     = relf[b * Hd + h];
        g_rin[b * 3 * Hd + 2 * Hd + h] = g_pooled[b * Hd + h];
    }
}

// ---------------- launch ----------------
extern "C" void kernel_launch(void* const* d_in, const int* in_sizes, int n_in,
                              void* d_out, int out_size)
{
    const float* hid    = (const float*)d_in[0];
    const float* ent    = (const float*)d_in[1];
    const float* ee_w1  = (const float*)d_in[2];
    const float* ee_b1  = (const float*)d_in[3];
    const float* ee_w2  = (const float*)d_in[4];
    const float* ee_b2  = (const float*)d_in[5];
    const float* ee_g   = (const float*)d_in[6];
    const float* ee_be  = (const float*)d_in[7];
    const float* re_w1  = (const float*)d_in[8];
    const float* re_b1  = (const float*)d_in[9];
    const float* re_w2  = (const float*)d_in[10];
    const float* re_b2  = (const float*)d_in[11];
    const float* re_g   = (const float*)d_in[12];
    const float* re_be  = (const float*)d_in[13];
    const float* rn_w1  = (const float*)d_in[14];
    const float* rn_b1  = (const float*)d_in[15];
    const float* rn_w2  = (const float*)d_in[16];
    const float* rn_b2  = (const float*)d_in[17];
    const float* rn_g   = (const float*)d_in[18];
    const float* rn_be  = (const float*)d_in[19];
    const float* vn_w1  = (const float*)d_in[20];
    const float* vn_b1  = (const float*)d_in[21];
    const float* vn_w2  = (const float*)d_in[22];
    const float* vn_b2  = (const float*)d_in[23];
    float* out = (float*)d_out;

    __half *ah, *mh, *wt1, *wt2;
    float *pooled, *rmid, *rraw, *rin, *rmid2, *vmid;
    cudaGetSymbolAddress((void**)&ah,  g_ah);
    cudaGetSymbolAddress((void**)&mh,  g_mh);
    cudaGetSymbolAddress((void**)&wt1, g_wt1);
    cudaGetSymbolAddress((void**)&wt2, g_wt2);
    cudaGetSymbolAddress((void**)&pooled, g_pooled);
    cudaGetSymbolAddress((void**)&rmid,   g_rmid);
    cudaGetSymbolAddress((void**)&rraw,   g_rraw);
    cudaGetSymbolAddress((void**)&rin,    g_rin);
    cudaGetSymbolAddress((void**)&rmid2,  g_rmid2);
    cudaGetSymbolAddress((void**)&vmid,   g_vmid);

    cudaFuncSetAttribute(gemm_tc<Hd, 2*Hd>,
                         cudaFuncAttributeMaxDynamicSharedMemorySize, GSMEM);
    cudaFuncSetAttribute(gemm_tc<2*Hd, Hd>,
                         cudaFuncAttributeMaxDynamicSharedMemorySize, GSMEM);

    // one-time host resources (no device memory involved)
    static cudaStream_t s2 = nullptr, s3 = nullptr;
    static cudaEvent_t evPrep = nullptr, evJoinB = nullptr, evJoinH1 = nullptr;
    if (!s2) {
        cudaStreamCreateWithFlags(&s2, cudaStreamNonBlocking);
        cudaStreamCreateWithFlags(&s3, cudaStreamNonBlocking);
        cudaEventCreateWithFlags(&evPrep,   cudaEventDisableTiming);
        cudaEventCreateWithFlags(&evJoinB,  cudaEventDisableTiming);
        cudaEventCreateWithFlags(&evJoinH1, cudaEventDisableTiming);
    }

    const int MH = MTOK / 2;   // 8192 rows per half

    // ---- fork: side streams join the capture ----
    cudaEventRecord(evPrep, 0);            // initial fork marker
    cudaStreamWaitEvent(s2, evPrep, 0);

    // ================= Chain B (stream s2): pooled path =========================
    pool_partial<<<dim3(32, PSEG), 256, 0, s2>>>(hid);
    pool_combine<<<32, 256, 0, s2>>>();
    sg_partial<<<dim3(Hd / 256, KSPLIT), 256, 0, s2>>>(pooled, re_w1, Hd, Hd);
    sg_combine<<<(8 * Hd + 255) / 256, 256, 0, s2>>>(re_b1, rmid, Hd, 1);
    sg_partial<<<dim3(Hd / 256, KSPLIT), 256, 0, s2>>>(rmid, re_w2, Hd, Hd);
    sg_combine<<<(8 * Hd + 255) / 256, 256, 0, s2>>>(re_b2, rraw, Hd, 0);
    ln_rows<<<BATCH, 256, 0, s2>>>(rraw, re_g, re_be, out + RF_OFF);
    sims_kernel<<<NENT, 128, 0, s2>>>(ent, out + RF_OFF, out + SIM_OFF);
    topk_kernel<<<BATCH, 256, 0, s2>>>(out + SIM_OFF, out + IDX_OFF);
    build_rin<<<BATCH, 256, 0, s2>>>(ent, out + RF_OFF, out + RET_OFF);
    sg_partial<<<dim3(2 * Hd / 256, KSPLIT), 256, 0, s2>>>(rin, rn_w1, 3 * Hd, 2 * Hd);
    sg_combine<<<(8 * 2 * Hd + 255) / 256, 256, 0, s2>>>(rn_b1, rmid2, 2 * Hd, 1);
    sg_partial<<<dim3(Hd / 256, KSPLIT), 256, 0, s2>>>(rmid2, rn_w2, 2 * Hd, Hd);
    sg_combine<<<(8 * Hd + 255) / 256, 256, 0, s2>>>(rn_b2, rraw, Hd, 0);
    ln_rows<<<BATCH, 256, 0, s2>>>(rraw, rn_g, rn_be, out + RO_OFF);
    sg_partial<<<dim3(512 / 256, KSPLIT), 256, 0, s2>>>(out + RO_OFF, vn_w1, Hd, 512);
    sg_combine<<<(8 * 512 + 255) / 256, 256, 0, s2>>>(vn_b1, vmid, 512, 1);
    sg_partial<<<dim3(1, KSPLIT), 256, 0, s2>>>(vmid, vn_w2, 512, 1);
    sg_combine<<<1, 256, 0, s2>>>(vn_b2, out + VS_OFF, 1, 2);

    // ================= Chain A prep (default stream) ============================
    convert_h16<<<(MTOK * Hd / 4 + 255) / 256, 256>>>(hid, ah, MTOK * Hd / 4);
    transpose_h16<<<dim3(2 * Hd / 32, Hd / 32), 256>>>(ee_w1, wt1, Hd, 2 * Hd);
    transpose_h16<<<dim3(Hd / 32, 2 * Hd / 32), 256>>>(ee_w2, wt2, 2 * Hd, Hd);
    cudaEventRecord(evPrep, 0);
    cudaStreamWaitEvent(s3, evPrep, 0);

    // ---- half 0 on default stream ----
    gemm_tc<Hd, 2*Hd><<<dim3(2 * Hd / 128, MH / 128), 256, GSMEM>>>(
        ah, wt1, ee_b1, nullptr, mh, 0, 1);
    gemm_tc<2*Hd, Hd><<<dim3(Hd / 128, MH / 128), 256, GSMEM>>>(
        mh, wt2, ee_b2, out + EF_OFF, nullptr, 0, 0);
    ln_rows<<<MH, 256>>>(out + EF_OFF, ee_g, ee_be, out + EF_OFF);

    // ---- half 1 on s3 ----
    gemm_tc<Hd, 2*Hd><<<dim3(2 * Hd / 128, MH / 128), 256, GSMEM, s3>>>(
        ah, wt1, ee_b1, nullptr, mh, MH, 1);
    gemm_tc<2*Hd, Hd><<<dim3(Hd / 128, MH / 128), 256, GSMEM, s3>>>(
        mh, wt2, ee_b2, out + EF_OFF, nullptr, MH, 0);
    ln_rows<<<MH, 256, 0, s3>>>(out + EF_OFF + (size_t)MH * Hd, ee_g, ee_be,
                                out + EF_OFF + (size_t)MH * Hd);

    // ---- join: default stream waits for Chain B and half 1 ----
    cudaEventRecord(evJoinB, s2);
    cudaStreamWaitEvent(0, evJoinB, 0);
    cudaEventRecord(evJoinH1, s3);
    cudaStreamWaitEvent(0, evJoinH1, 0);
}

// round 16
// speedup vs baseline: 1.2098x; 1.1632x over previous
#include <cuda_runtime.h>
#include <cuda_fp16.h>
#include <mma.h>
#include <math.h>
#include <stdint.h>

using namespace nvcuda;

// ---------------- constants ----------------
#define Hd   1024
#define BATCH 8
#define SEQ  2048
#define MTOK (BATCH*SEQ)        // 16384
#define NENT 1000
#define TOPK 5
#define LNEPS 1e-5f
#define NEG_INF -3.4e38f

// output layout (floats), concatenated in reference return order
#define EF_OFF  0                         // entity_features  [8,2048,1024]
#define RF_OFF  (EF_OFF + MTOK*Hd)        // relation_features [8,1024]
#define RET_OFF (RF_OFF + BATCH*Hd)       // retrieved_entities [8,5,1024]
#define SIM_OFF (RET_OFF + BATCH*TOPK*Hd) // entity_similarities [8,1000]
#define IDX_OFF (SIM_OFF + BATCH*NENT)    // top_indices [8,5] (as float)
#define RO_OFF  (IDX_OFF + BATCH*TOPK)    // reasoning_output [8,1024]
#define VS_OFF  (RO_OFF + BATCH*Hd)       // validation_scores [8,1]

// ---------------- scratch (static device memory; no allocations) ----------------
__device__ __align__(128) __half g_ah[(size_t)MTOK * Hd];
__device__ __align__(128) __half g_mh[(size_t)MTOK * 2*Hd];
__device__ __align__(128) __half g_wt1[2*Hd * Hd];   // ee_w1^T fp16 [2048][1024]
__device__ __align__(128) __half g_wt2[Hd * 2*Hd];   // ee_w2^T fp16 [1024][2048]

#define PSEG 64
__device__ float g_pool_part[PSEG * BATCH*Hd];
__device__ float g_pooled[BATCH*Hd];
__device__ float g_part[8 * 8 * 2048];
__device__ float g_rmid[BATCH*Hd];
__device__ float g_rraw[BATCH*Hd];
__device__ float g_rin[BATCH*3*Hd];
__device__ float g_rmid2[BATCH*2*Hd];
__device__ float g_vmid[BATCH*512];
__device__ int   g_topidx[BATCH*TOPK];

// ---------------- math helpers ----------------
__device__ __forceinline__ float gelu_erf(float x) {
    return 0.5f * x * (1.0f + erff(x * 0.70710678118654752f));
}
__device__ __forceinline__ float sigmoidf_(float x) {
    return 1.0f / (1.0f + expf(-x));
}
__device__ __forceinline__ float apply_act(float v, int act) {
    if (act == 1) return gelu_erf(v);
    if (act == 2) return sigmoidf_(v);
    return v;
}

// ---------------- conversions ----------------
__global__ __launch_bounds__(256) void convert_h16(
    const float* __restrict__ x, __half* __restrict__ h, int n4)
{
    int i = blockIdx.x * 256 + threadIdx.x;
    if (i >= n4) return;
    float4 v = ((const float4*)x)[i];
    __half2* H = (__half2*)(h + 4*(size_t)i);
    H[0] = __half2(__float2half_rn(v.x), __float2half_rn(v.y));
    H[1] = __half2(__float2half_rn(v.z), __float2half_rn(v.w));
}

// W[K][N] fp32 -> WT fp16 [N][K]
__global__ __launch_bounds__(256) void transpose_h16(
    const float* __restrict__ W, __half* __restrict__ th, int K, int N)
{
    __shared__ float t[32][33];
    int n0 = blockIdx.x * 32, k0 = blockIdx.y * 32;
    int tx = threadIdx.x & 31, ty = threadIdx.x >> 5;   // 32x8
#pragma unroll
    for (int r = 0; r < 32; r += 8)
        t[ty + r][tx] = W[(size_t)(k0 + ty + r) * N + n0 + tx];
    __syncthreads();
#pragma unroll
    for (int r = 0; r < 32; r += 8)
        th[(size_t)(n0 + ty + r) * K + k0 + tx] = __float2half_rn(t[tx][ty + r]);
}

// ---------------- WMMA fp16 GEMM (128x128 block, 32x64 warp tiles) --------------
// C[M][N] = act(A @ B^T + bias), A [M][K] fp16, B rows [N][K] fp16, fp32 accum.
// row_off: M offset of this launch's slab. mode 0: fp32 C. mode 1: gelu -> fp16 C.
#define BKC 32
#define LDK 40                               // fp16 leading dim with pad (80B row)
#define TILEB (128 * LDK * 2)                // 10240 B per operand tile
#define STAGEB (2 * TILEB)                   // Ah, Bh = 20480 B
#define GSMEM 40960                          // max(2*STAGEB, 64*LDC*4=33792)
#define LDC 132

__device__ __forceinline__ void cpa16(void* s, const void* g) {
    uint32_t sa;
    asm("{ .reg .u64 tmp; cvta.to.shared.u64 tmp, %1; cvt.u32.u64 %0, tmp; }"
        : "=r"(sa) : "l"(s));
    asm volatile("cp.async.cg.shared.global [%0], [%1], 16;" :: "r"(sa), "l"(g) : "memory");
}

template<int K>
__device__ __forceinline__ void load_tile_async(
    const __half* __restrict__ g, int row0, int kc, char* s, int tid)
{
    int r = tid >> 2, c = tid & 3;
#pragma unroll
    for (int h = 0; h < 2; h++) {
        int row = r + h * 64;
        cpa16(s + row * (LDK * 2) + c * 16,
              g + (size_t)(row0 + row) * K + kc + c * 8);
    }
}

template<int K>
__device__ __forceinline__ void stage_loads(
    const __half* ah, const __half* bh,
    int bm, int bn, int kc, char* st, int tid)
{
    load_tile_async<K>(ah, bm, kc, st + 0*TILEB, tid);
    load_tile_async<K>(bh, bn, kc, st + 1*TILEB, tid);
    asm volatile("cp.async.commit_group;" ::: "memory");
}

template<int K, int N>
__global__ __launch_bounds__(256) void gemm_tc(
    const __half* __restrict__ ah_g, const __half* __restrict__ bh_g,
    const float* __restrict__ bias,
    float* __restrict__ Cf, __half* __restrict__ ch_out,
    int row_off, int mode)
{
    extern __shared__ char sm_[];
    const int tid = threadIdx.x;
    const int wid = tid >> 5;
    const int wm = wid & 3;          // 4 warps along M (32 rows each)
    const int wn = wid >> 2;         // 2 warps along N (64 cols each)
    const int bn = blockIdx.x * 128;
    const int bm = row_off + blockIdx.y * 128;

    wmma::fragment<wmma::accumulator, 16, 16, 16, float> acc[2][4];
#pragma unroll
    for (int mi = 0; mi < 2; mi++)
#pragma unroll
        for (int ni = 0; ni < 4; ni++) wmma::fill_fragment(acc[mi][ni], 0.0f);

    constexpr int NCH = K / BKC;

    stage_loads<K>(ah_g, bh_g, bm, bn, 0, sm_, tid);

    for (int ch = 0; ch < NCH; ch++) {
        if (ch + 1 < NCH) {
            stage_loads<K>(ah_g, bh_g, bm, bn, (ch + 1) * BKC,
                           sm_ + ((ch + 1) & 1) * STAGEB, tid);
            asm volatile("cp.async.wait_group 1;" ::: "memory");
        } else {
            asm volatile("cp.async.wait_group 0;" ::: "memory");
        }
        __syncthreads();

        char* st = sm_ + (ch & 1) * STAGEB;
        const __half* Ah = (const __half*)(st + 0*TILEB);
        const __half* Bh = (const __half*)(st + 1*TILEB);

#pragma unroll
        for (int kk = 0; kk < BKC; kk += 16) {
            wmma::fragment<wmma::matrix_a, 16, 16, 16, __half, wmma::row_major> af[2];
            wmma::fragment<wmma::matrix_b, 16, 16, 16, __half, wmma::col_major> bf[4];
#pragma unroll
            for (int mi = 0; mi < 2; mi++)
                wmma::load_matrix_sync(af[mi], Ah + (wm * 32 + mi * 16) * LDK + kk, LDK);
#pragma unroll
            for (int ni = 0; ni < 4; ni++)
                wmma::load_matrix_sync(bf[ni], Bh + (wn * 64 + ni * 16) * LDK + kk, LDK);
#pragma unroll
            for (int mi = 0; mi < 2; mi++)
#pragma unroll
                for (int ni = 0; ni < 4; ni++)
                    wmma::mma_sync(acc[mi][ni], af[mi], bf[ni], acc[mi][ni]);
        }
        __syncthreads();
    }

    // ---- epilogue in two 64-row slabs (reuses mainloop SMEM) ----
    float* Cs = (float*)sm_;                 // 64 x LDC fp32 = 33792 B
#pragma unroll
    for (int mi = 0; mi < 2; mi++) {
#pragma unroll
        for (int ni = 0; ni < 4; ni++)
            wmma::store_matrix_sync(Cs + (wm * 16) * LDC + wn * 64 + ni * 16,
                                    acc[mi][ni], LDC, wmma::mem_row_major);
        __syncthreads();

        for (int i = tid; i < 64 * 32; i += 256) {
            int srow = i >> 5;
            int col = (i & 31) * 4;
            int grow = bm + (srow >> 4) * 32 + mi * 16 + (srow & 15);
            float4 v = *(float4*)&Cs[srow * LDC + col];
            v.x += bias[bn + col + 0];
            v.y += bias[bn + col + 1];
            v.z += bias[bn + col + 2];
            v.w += bias[bn + col + 3];
            size_t o = (size_t)grow * N + bn + col;
            if (mode == 0) {
                *(float4*)&Cf[o] = v;
            } else {
                __half2* H = (__half2*)(ch_out + o);
                H[0] = __half2(__float2half_rn(gelu_erf(v.x)),
                               __float2half_rn(gelu_erf(v.y)));
                H[1] = __half2(__float2half_rn(gelu_erf(v.z)),
                               __float2half_rn(gelu_erf(v.w)));
            }
        }
        __syncthreads();
    }
}

// ---------------- per-row LayerNorm over H=1024 (in-place safe) ----------------
__global__ __launch_bounds__(256) void ln_rows(
    const float* __restrict__ X, const float* __restrict__ g,
    const float* __restrict__ beta, float* __restrict__ Y)
{
    const int row = blockIdx.x;
    const int tid = threadIdx.x;
    const float* x = X + (size_t)row * Hd;
    float v[4];
    float s = 0.0f, q = 0.0f;
#pragma unroll
    for (int i = 0; i < 4; i++) {
        v[i] = x[tid + i * 256];
        s += v[i];
        q += v[i] * v[i];
    }
    __shared__ float sh1[256], sh2[256];
    sh1[tid] = s; sh2[tid] = q;
    __syncthreads();
    for (int o = 128; o; o >>= 1) {
        if (tid < o) { sh1[tid] += sh1[tid + o]; sh2[tid] += sh2[tid + o]; }
        __syncthreads();
    }
    float mu = sh1[0] * (1.0f / Hd);
    float var = sh2[0] * (1.0f / Hd) - mu * mu;
    float inv = rsqrtf(var + LNEPS);
    float* y = Y + (size_t)row * Hd;
#pragma unroll
    for (int i = 0; i < 4; i++) {
        int c = tid + i * 256;
        y[c] = (v[i] - mu) * inv * g[c] + beta[c];
    }
}

// ---------------- mean pool over sequence ----------------
__global__ void pool_partial(const float* __restrict__ hid)
{
    int idx = blockIdx.x * 256 + threadIdx.x;   // 0..8191
    int ss = blockIdx.y;                        // 0..PSEG-1
    int b = idx >> 10, h = idx & 1023;
    float s = 0.0f;
    int s0 = ss * (SEQ / PSEG);
    const float* base = hid + ((size_t)b * SEQ + s0) * Hd + h;
#pragma unroll 4
    for (int t = 0; t < SEQ / PSEG; t++) s += base[(size_t)t * Hd];
    g_pool_part[ss * (BATCH * Hd) + idx] = s;
}
__global__ void pool_combine()
{
    int idx = blockIdx.x * 256 + threadIdx.x;
    float s = 0.0f;
#pragma unroll
    for (int ss = 0; ss < PSEG; ss++) s += g_pool_part[ss * (BATCH * Hd) + idx];
    g_pooled[idx] = s * (1.0f / SEQ);
}

// ---------------- small GEMM (8 rows) with deterministic K-split ----------------
#define KSPLIT 8
__global__ void sg_partial(const float* __restrict__ X, const float* __restrict__ W,
                           int K, int N)
{
    int n = blockIdx.x * blockDim.x + threadIdx.x;
    int ks = blockIdx.y;
    if (n >= N) return;
    int kchunk = K / KSPLIT;
    int k0 = ks * kchunk, k1 = k0 + kchunk;
    float acc[8];
#pragma unroll
    for (int r = 0; r < 8; r++) acc[r] = 0.0f;
    for (int k = k0; k < k1; k++) {
        float w = W[(size_t)k * N + n];
#pragma unroll
        for (int r = 0; r < 8; r++) acc[r] = fmaf(__ldg(&X[r * K + k]), w, acc[r]);
    }
#pragma unroll
    for (int r = 0; r < 8; r++) g_part[(ks * 8 + r) * N + n] = acc[r];
}
__global__ void sg_combine(const float* __restrict__ bias, float* __restrict__ Y,
                           int N, int act)
{
    int i = blockIdx.x * blockDim.x + threadIdx.x;
    if (i >= 8 * N) return;
    int r = i / N, n = i - r * N;
    float s = bias[n];
#pragma unroll
    for (int ks = 0; ks < KSPLIT; ks++) s += g_part[(ks * 8 + r) * N + n];
    Y[i] = apply_act(s, act);
}

// ---------------- entity similarities ----------------
__global__ __launch_bounds__(128) void sims_kernel(
    const float* __restrict__ E, const float* __restrict__ relf,
    float* __restrict__ sims)
{
    int n = blockIdx.x;
    int tid = threadIdx.x;
    __shared__ float rs[BATCH * Hd];
    for (int i = tid; i < BATCH * Hd; i += 128) rs[i] = relf[i];
    __syncthreads();
    float acc[8];
#pragma unroll
    for (int r = 0; r < 8; r++) acc[r] = 0.0f;
    for (int k = tid; k < Hd; k += 128) {
        float e = E[(size_t)n * Hd + k];
#pragma unroll
        for (int r = 0; r < 8; r++) acc[r] = fmaf(e, rs[r * Hd + k], acc[r]);
    }
    __shared__ float red[8][128];
#pragma unroll
    for (int r = 0; r < 8; r++) red[r][tid] = acc[r];
    __syncthreads();
    for (int o = 64; o; o >>= 1) {
        if (tid < o) {
#pragma unroll
            for (int r = 0; r < 8; r++) red[r][tid] += red[r][tid + o];
        }
        __syncthreads();
    }
    if (tid < 8) sims[tid * NENT + n] = red[tid][0];
}

// ---------------- top-5 (desc, lowest index on ties) ----------------
__global__ __launch_bounds__(256) void topk_kernel(const float* __restrict__ sims,
                                                   float* __restrict__ fidx_out)
{
    int b = blockIdx.x;
    int tid = threadIdx.x;
    __shared__ float sv[1024];
    for (int i = tid; i < 1024; i += 256)
        sv[i] = (i < NENT) ? sims[b * NENT + i] : NEG_INF;
    __syncthreads();
    __shared__ float bv[256];
    __shared__ int bi[256];
    for (int t = 0; t < TOPK; t++) {
        float best = NEG_INF; int besti = 0;
        for (int i = tid; i < NENT; i += 256) {
            float vv = sv[i];
            if (vv > best) { best = vv; besti = i; }
        }
        bv[tid] = best; bi[tid] = besti;
        __syncthreads();
        for (int o = 128; o; o >>= 1) {
            if (tid < o) {
                if (bv[tid + o] > bv[tid] ||
                    (bv[tid + o] == bv[tid] && bi[tid + o] < bi[tid])) {
                    bv[tid] = bv[tid + o]; bi[tid] = bi[tid + o];
                }
            }
            __syncthreads();
        }
        if (tid == 0) {
            g_topidx[b * TOPK + t] = bi[0];
            fidx_out[b * TOPK + t] = (float)bi[0];
            sv[bi[0]] = NEG_INF;
        }
        __syncthreads();
    }
}

// ---------------- gather retrieved entities + build reasoning input ----------------
__global__ __launch_bounds__(256) void build_rin(
    const float* __restrict__ E, const float* __restrict__ relf,
    float* __restrict__ ret_out)
{
    int b = blockIdx.x;
    for (int h = threadIdx.x; h < Hd; h += 256) {
        float s = 0.0f;
#pragma unroll
        for (int k = 0; k < TOPK; k++) {
            float v = E[(size_t)g_topidx[b * TOPK + k] * Hd + h];
            ret_out[((size_t)b * TOPK + k) * Hd + h] = v;
            s += v;
        }
        g_rin[b * 3 * Hd + h]          = s * (1.0f / TOPK);
        g_rin[b * 3 * Hd + Hd + h]     = relf[b * Hd + h];
        g_rin[b * 3 * Hd + 2 * Hd + h] = g_pooled[b * Hd + h];
    }
}

// ---------------- launch ----------------
extern "C" void kernel_launch(void* const* d_in, const int* in_sizes, int n_in,
                              void* d_out, int out_size)
{
    const float* hid    = (const float*)d_in[0];
    const float* ent    = (const float*)d_in[1];
    const float* ee_w1  = (const float*)d_in[2];
    const float* ee_b1  = (const float*)d_in[3];
    const float* ee_w2  = (const float*)d_in[4];
    const float* ee_b2  = (const float*)d_in[5];
    const float* ee_g   = (const float*)d_in[6];
    const float* ee_be  = (const float*)d_in[7];
    const float* re_w1  = (const float*)d_in[8];
    const float* re_b1  = (const float*)d_in[9];
    const float* re_w2  = (const float*)d_in[10];
    const float* re_b2  = (const float*)d_in[11];
    const float* re_g   = (const float*)d_in[12];
    const float* re_be  = (const float*)d_in[13];
    const float* rn_w1  = (const float*)d_in[14];
    const float* rn_b1  = (const float*)d_in[15];
    const float* rn_w2  = (const float*)d_in[16];
    const float* rn_b2  = (const float*)d_in[17];
    const float* rn_g   = (const float*)d_in[18];
    const float* rn_be  = (const float*)d_in[19];
    const float* vn_w1  = (const float*)d_in[20];
    const float* vn_b1  = (const float*)d_in[21];
    const float* vn_w2  = (const float*)d_in[22];
    const float* vn_b2  = (const float*)d_in[23];
    float* out = (float*)d_out;

    __half *ah, *mh, *wt1, *wt2;
    float *pooled, *rmid, *rraw, *rin, *rmid2, *vmid;
    cudaGetSymbolAddress((void**)&ah,  g_ah);
    cudaGetSymbolAddress((void**)&mh,  g_mh);
    cudaGetSymbolAddress((void**)&wt1, g_wt1);
    cudaGetSymbolAddress((void**)&wt2, g_wt2);
    cudaGetSymbolAddress((void**)&pooled, g_pooled);
    cudaGetSymbolAddress((void**)&rmid,   g_rmid);
    cudaGetSymbolAddress((void**)&rraw,   g_rraw);
    cudaGetSymbolAddress((void**)&rin,    g_rin);
    cudaGetSymbolAddress((void**)&rmid2,  g_rmid2);
    cudaGetSymbolAddress((void**)&vmid,   g_vmid);

    cudaFuncSetAttribute(gemm_tc<Hd, 2*Hd>,
                         cudaFuncAttributeMaxDynamicSharedMemorySize, GSMEM);
    cudaFuncSetAttribute(gemm_tc<2*Hd, Hd>,
                         cudaFuncAttributeMaxDynamicSharedMemorySize, GSMEM);

    // one-time host resources (no device memory involved)
    static cudaStream_t s2 = nullptr, s3 = nullptr;
    static cudaEvent_t evPrep = nullptr, evJoinB = nullptr, evJoinH1 = nullptr;
    if (!s2) {
        cudaStreamCreateWithFlags(&s2, cudaStreamNonBlocking);
        cudaStreamCreateWithFlags(&s3, cudaStreamNonBlocking);
        cudaEventCreateWithFlags(&evPrep,   cudaEventDisableTiming);
        cudaEventCreateWithFlags(&evJoinB,  cudaEventDisableTiming);
        cudaEventCreateWithFlags(&evJoinH1, cudaEventDisableTiming);
    }

    const int NSLAB = 4;
    const int MS = MTOK / NSLAB;   // 4096 rows per slab

    // ---- fork: side streams join the capture ----
    cudaEventRecord(evPrep, 0);            // initial fork marker
    cudaStreamWaitEvent(s2, evPrep, 0);
    cudaStreamWaitEvent(s3, evPrep, 0);

    // ================= Chain B (stream s2): pooled path =========================
    pool_partial<<<dim3(32, PSEG), 256, 0, s2>>>(hid);
    pool_combine<<<32, 256, 0, s2>>>();
    sg_partial<<<dim3(Hd / 256, KSPLIT), 256, 0, s2>>>(pooled, re_w1, Hd, Hd);
    sg_combine<<<(8 * Hd + 255) / 256, 256, 0, s2>>>(re_b1, rmid, Hd, 1);
    sg_partial<<<dim3(Hd / 256, KSPLIT), 256, 0, s2>>>(rmid, re_w2, Hd, Hd);
    sg_combine<<<(8 * Hd + 255) / 256, 256, 0, s2>>>(re_b2, rraw, Hd, 0);
    ln_rows<<<BATCH, 256, 0, s2>>>(rraw, re_g, re_be, out + RF_OFF);
    sims_kernel<<<NENT, 128, 0, s2>>>(ent, out + RF_OFF, out + SIM_OFF);
    topk_kernel<<<BATCH, 256, 0, s2>>>(out + SIM_OFF, out + IDX_OFF);
    build_rin<<<BATCH, 256, 0, s2>>>(ent, out + RF_OFF, out + RET_OFF);
    sg_partial<<<dim3(2 * Hd / 256, KSPLIT), 256, 0, s2>>>(rin, rn_w1, 3 * Hd, 2 * Hd);
    sg_combine<<<(8 * 2 * Hd + 255) / 256, 256, 0, s2>>>(rn_b1, rmid2, 2 * Hd, 1);
    sg_partial<<<dim3(Hd / 256, KSPLIT), 256, 0, s2>>>(rmid2, rn_w2, 2 * Hd, Hd);
    sg_combine<<<(8 * Hd + 255) / 256, 256, 0, s2>>>(rn_b2, rraw, Hd, 0);
    ln_rows<<<BATCH, 256, 0, s2>>>(rraw, rn_g, rn_be, out + RO_OFF);
    sg_partial<<<dim3(512 / 256, KSPLIT), 256, 0, s2>>>(out + RO_OFF, vn_w1, Hd, 512);
    sg_combine<<<(8 * 512 + 255) / 256, 256, 0, s2>>>(vn_b1, vmid, 512, 1);
    sg_partial<<<dim3(1, KSPLIT), 256, 0, s2>>>(vmid, vn_w2, 512, 1);
    sg_combine<<<1, 256, 0, s2>>>(vn_b2, out + VS_OFF, 1, 2);

    // ================= Chain A prep (default stream) ============================
    transpose_h16<<<dim3(2 * Hd / 32, Hd / 32), 256>>>(ee_w1, wt1, Hd, 2 * Hd);
    transpose_h16<<<dim3(Hd / 32, 2 * Hd / 32), 256>>>(ee_w2, wt2, 2 * Hd, Hd);
    cudaEventRecord(evPrep, 0);            // weights ready
    cudaStreamWaitEvent(s3, evPrep, 0);

    // ---- 4 slab-chains, alternating streams 0 / s3 ----
    for (int s = 0; s < NSLAB; s++) {
        cudaStream_t st = (s & 1) ? s3 : (cudaStream_t)0;
        int row0 = s * MS;
        convert_h16<<<(MS * Hd / 4 + 255) / 256, 256, 0, st>>>(
            hid + (size_t)row0 * Hd, ah + (size_t)row0 * Hd, MS * Hd / 4);
        gemm_tc<Hd, 2*Hd><<<dim3(2 * Hd / 128, MS / 128), 256, GSMEM, st>>>(
            ah, wt1, ee_b1, nullptr, mh, row0, 1);
        gemm_tc<2*Hd, Hd><<<dim3(Hd / 128, MS / 128), 256, GSMEM, st>>>(
            mh, wt2, ee_b2, out + EF_OFF, nullptr, row0, 0);
        ln_rows<<<MS, 256, 0, st>>>(out + EF_OFF + (size_t)row0 * Hd, ee_g, ee_be,
                                    out + EF_OFF + (size_t)row0 * Hd);
    }

    // ---- join: default stream waits for Chain B and s3 ----
    cudaEventRecord(evJoinB, s2);
    cudaStreamWaitEvent(0, evJoinB, 0);
    cudaEventRecord(evJoinH1, s3);
    cudaStreamWaitEvent(0, evJoinH1, 0);
}

// round 17
// speedup vs baseline: 1.2461x; 1.0300x over previous
#include <cuda_runtime.h>
#include <cuda_fp16.h>
#include <mma.h>
#include <math.h>
#include <stdint.h>

using namespace nvcuda;

// ---------------- constants ----------------
#define Hd   1024
#define BATCH 8
#define SEQ  2048
#define MTOK (BATCH*SEQ)        // 16384
#define NENT 1000
#define TOPK 5
#define LNEPS 1e-5f
#define NEG_INF -3.4e38f

// output layout (floats), concatenated in reference return order
#define EF_OFF  0                         // entity_features  [8,2048,1024]
#define RF_OFF  (EF_OFF + MTOK*Hd)        // relation_features [8,1024]
#define RET_OFF (RF_OFF + BATCH*Hd)       // retrieved_entities [8,5,1024]
#define SIM_OFF (RET_OFF + BATCH*TOPK*Hd) // entity_similarities [8,1000]
#define IDX_OFF (SIM_OFF + BATCH*NENT)    // top_indices [8,5] (as float)
#define RO_OFF  (IDX_OFF + BATCH*TOPK)    // reasoning_output [8,1024]
#define VS_OFF  (RO_OFF + BATCH*Hd)       // validation_scores [8,1]

// ---------------- scratch (static device memory; no allocations) ----------------
__device__ __align__(128) __half g_ah[(size_t)MTOK * Hd];
__device__ __align__(128) __half g_mh[(size_t)MTOK * 2*Hd];
__device__ __align__(128) __half g_wt1[2*Hd * Hd];   // ee_w1^T fp16 [2048][1024]
__device__ __align__(128) __half g_wt2[Hd * 2*Hd];   // ee_w2^T fp16 [1024][2048]

#define PSEG 64
__device__ float g_pool_part[PSEG * BATCH*Hd];
__device__ float g_pooled[BATCH*Hd];
__device__ float g_part[8 * 8 * 2048];
__device__ float g_rmid[BATCH*Hd];
__device__ float g_rraw[BATCH*Hd];
__device__ float g_rin[BATCH*3*Hd];
__device__ float g_rmid2[BATCH*2*Hd];
__device__ float g_vmid[BATCH*512];
__device__ int   g_topidx[BATCH*TOPK];

// ---------------- math helpers ----------------
__device__ __forceinline__ float gelu_erf(float x) {
    return 0.5f * x * (1.0f + erff(x * 0.70710678118654752f));
}
__device__ __forceinline__ float sigmoidf_(float x) {
    return 1.0f / (1.0f + expf(-x));
}
__device__ __forceinline__ float apply_act(float v, int act) {
    if (act == 1) return gelu_erf(v);
    if (act == 2) return sigmoidf_(v);
    return v;
}

// ---------------- conversions ----------------
__global__ __launch_bounds__(256) void convert_h16(
    const float* __restrict__ x, __half* __restrict__ h, int n4)
{
    int i = blockIdx.x * 256 + threadIdx.x;
    if (i >= n4) return;
    float4 v = ((const float4*)x)[i];
    __half2* H = (__half2*)(h + 4*(size_t)i);
    H[0] = __half2(__float2half_rn(v.x), __float2half_rn(v.y));
    H[1] = __half2(__float2half_rn(v.z), __float2half_rn(v.w));
}

// W[K][N] fp32 -> WT fp16 [N][K]
__global__ __launch_bounds__(256) void transpose_h16(
    const float* __restrict__ W, __half* __restrict__ th, int K, int N)
{
    __shared__ float t[32][33];
    int n0 = blockIdx.x * 32, k0 = blockIdx.y * 32;
    int tx = threadIdx.x & 31, ty = threadIdx.x >> 5;   // 32x8
#pragma unroll
    for (int r = 0; r < 32; r += 8)
        t[ty + r][tx] = W[(size_t)(k0 + ty + r) * N + n0 + tx];
    __syncthreads();
#pragma unroll
    for (int r = 0; r < 32; r += 8)
        th[(size_t)(n0 + ty + r) * K + k0 + tx] = __float2half_rn(t[tx][ty + r]);
}

// ---------------- WMMA fp16 GEMM (128x128 block, 32x64 warp tiles) --------------
// C[M][N] = act(A @ B^T + bias), A [M][K] fp16, B rows [N][K] fp16, fp32 accum.
// row_off: M offset of this launch's slab. mode 0: fp32 C. mode 1: gelu -> fp16 C.
#define BKC 32
#define LDK 40                               // fp16 leading dim with pad (80B row)
#define TILEB (128 * LDK * 2)                // 10240 B per operand tile
#define STAGEB (2 * TILEB)                   // Ah, Bh = 20480 B
#define GSMEM 40960                          // max(2*STAGEB, 64*LDC*4=33792)
#define LDC 132

__device__ __forceinline__ void cpa16(void* s, const void* g) {
    uint32_t sa;
    asm("{ .reg .u64 tmp; cvta.to.shared.u64 tmp, %1; cvt.u32.u64 %0, tmp; }"
        : "=r"(sa) : "l"(s));
    asm volatile("cp.async.cg.shared.global [%0], [%1], 16;" :: "r"(sa), "l"(g) : "memory");
}

template<int K>
__device__ __forceinline__ void load_tile_async(
    const __half* __restrict__ g, int row0, int kc, char* s, int tid)
{
    int r = tid >> 2, c = tid & 3;
#pragma unroll
    for (int h = 0; h < 2; h++) {
        int row = r + h * 64;
        cpa16(s + row * (LDK * 2) + c * 16,
              g + (size_t)(row0 + row) * K + kc + c * 8);
    }
}

template<int K>
__device__ __forceinline__ void stage_loads(
    const __half* ah, const __half* bh,
    int bm, int bn, int kc, char* st, int tid)
{
    load_tile_async<K>(ah, bm, kc, st + 0*TILEB, tid);
    load_tile_async<K>(bh, bn, kc, st + 1*TILEB, tid);
    asm volatile("cp.async.commit_group;" ::: "memory");
}

template<int K, int N>
__global__ __launch_bounds__(256) void gemm_tc(
    const __half* __restrict__ ah_g, const __half* __restrict__ bh_g,
    const float* __restrict__ bias,
    float* __restrict__ Cf, __half* __restrict__ ch_out,
    int row_off, int mode)
{
    extern __shared__ char sm_[];
    const int tid = threadIdx.x;
    const int wid = tid >> 5;
    const int wm = wid & 3;          // 4 warps along M (32 rows each)
    const int wn = wid >> 2;         // 2 warps along N (64 cols each)
    const int bn = blockIdx.x * 128;
    const int bm = row_off + blockIdx.y * 128;

    wmma::fragment<wmma::accumulator, 16, 16, 16, float> acc[2][4];
#pragma unroll
    for (int mi = 0; mi < 2; mi++)
#pragma unroll
        for (int ni = 0; ni < 4; ni++) wmma::fill_fragment(acc[mi][ni], 0.0f);

    constexpr int NCH = K / BKC;

    stage_loads<K>(ah_g, bh_g, bm, bn, 0, sm_, tid);

    for (int ch = 0; ch < NCH; ch++) {
        if (ch + 1 < NCH) {
            stage_loads<K>(ah_g, bh_g, bm, bn, (ch + 1) * BKC,
                           sm_ + ((ch + 1) & 1) * STAGEB, tid);
            asm volatile("cp.async.wait_group 1;" ::: "memory");
        } else {
            asm volatile("cp.async.wait_group 0;" ::: "memory");
        }
        __syncthreads();

        char* st = sm_ + (ch & 1) * STAGEB;
        const __half* Ah = (const __half*)(st + 0*TILEB);
        const __half* Bh = (const __half*)(st + 1*TILEB);

#pragma unroll
        for (int kk = 0; kk < BKC; kk += 16) {
            wmma::fragment<wmma::matrix_a, 16, 16, 16, __half, wmma::row_major> af[2];
            wmma::fragment<wmma::matrix_b, 16, 16, 16, __half, wmma::col_major> bf[4];
#pragma unroll
            for (int mi = 0; mi < 2; mi++)
                wmma::load_matrix_sync(af[mi], Ah + (wm * 32 + mi * 16) * LDK + kk, LDK);
#pragma unroll
            for (int ni = 0; ni < 4; ni++)
                wmma::load_matrix_sync(bf[ni], Bh + (wn * 64 + ni * 16) * LDK + kk, LDK);
#pragma unroll
            for (int mi = 0; mi < 2; mi++)
#pragma unroll
                for (int ni = 0; ni < 4; ni++)
                    wmma::mma_sync(acc[mi][ni], af[mi], bf[ni], acc[mi][ni]);
        }
        __syncthreads();
    }

    // ---- epilogue in two 64-row slabs (reuses mainloop SMEM) ----
    float* Cs = (float*)sm_;                 // 64 x LDC fp32 = 33792 B
#pragma unroll
    for (int mi = 0; mi < 2; mi++) {
#pragma unroll
        for (int ni = 0; ni < 4; ni++)
            wmma::store_matrix_sync(Cs + (wm * 16) * LDC + wn * 64 + ni * 16,
                                    acc[mi][ni], LDC, wmma::mem_row_major);
        __syncthreads();

        for (int i = tid; i < 64 * 32; i += 256) {
            int srow = i >> 5;
            int col = (i & 31) * 4;
            int grow = bm + (srow >> 4) * 32 + mi * 16 + (srow & 15);
            float4 v = *(float4*)&Cs[srow * LDC + col];
            v.x += bias[bn + col + 0];
            v.y += bias[bn + col + 1];
            v.z += bias[bn + col + 2];
            v.w += bias[bn + col + 3];
            size_t o = (size_t)grow * N + bn + col;
            if (mode == 0) {
                *(float4*)&Cf[o] = v;
            } else {
                __half2* H = (__half2*)(ch_out + o);
                H[0] = __half2(__float2half_rn(gelu_erf(v.x)),
                               __float2half_rn(gelu_erf(v.y)));
                H[1] = __half2(__float2half_rn(gelu_erf(v.z)),
                               __float2half_rn(gelu_erf(v.w)));
            }
        }
        __syncthreads();
    }
}

// ---------------- per-row LayerNorm over H=1024 (in-place safe) ----------------
__global__ __launch_bounds__(256) void ln_rows(
    const float* __restrict__ X, const float* __restrict__ g,
    const float* __restrict__ beta, float* __restrict__ Y)
{
    const int row = blockIdx.x;
    const int tid = threadIdx.x;
    const float* x = X + (size_t)row * Hd;
    float v[4];
    float s = 0.0f, q = 0.0f;
#pragma unroll
    for (int i = 0; i < 4; i++) {
        v[i] = x[tid + i * 256];
        s += v[i];
        q += v[i] * v[i];
    }
    __shared__ float sh1[256], sh2[256];
    sh1[tid] = s; sh2[tid] = q;
    __syncthreads();
    for (int o = 128; o; o >>= 1) {
        if (tid < o) { sh1[tid] += sh1[tid + o]; sh2[tid] += sh2[tid + o]; }
        __syncthreads();
    }
    float mu = sh1[0] * (1.0f / Hd);
    float var = sh2[0] * (1.0f / Hd) - mu * mu;
    float inv = rsqrtf(var + LNEPS);
    float* y = Y + (size_t)row * Hd;
#pragma unroll
    for (int i = 0; i < 4; i++) {
        int c = tid + i * 256;
        y[c] = (v[i] - mu) * inv * g[c] + beta[c];
    }
}

// ---------------- mean pool over sequence ----------------
__global__ void pool_partial(const float* __restrict__ hid)
{
    int idx = blockIdx.x * 256 + threadIdx.x;   // 0..8191
    int ss = blockIdx.y;                        // 0..PSEG-1
    int b = idx >> 10, h = idx & 1023;
    float s = 0.0f;
    int s0 = ss * (SEQ / PSEG);
    const float* base = hid + ((size_t)b * SEQ + s0) * Hd + h;
#pragma unroll 4
    for (int t = 0; t < SEQ / PSEG; t++) s += base[(size_t)t * Hd];
    g_pool_part[ss * (BATCH * Hd) + idx] = s;
}
__global__ void pool_combine()
{
    int idx = blockIdx.x * 256 + threadIdx.x;
    float s = 0.0f;
#pragma unroll
    for (int ss = 0; ss < PSEG; ss++) s += g_pool_part[ss * (BATCH * Hd) + idx];
    g_pooled[idx] = s * (1.0f / SEQ);
}

// ---------------- small GEMM (8 rows) with deterministic K-split ----------------
#define KSPLIT 8
__global__ void sg_partial(const float* __restrict__ X, const float* __restrict__ W,
                           int K, int N)
{
    int n = blockIdx.x * blockDim.x + threadIdx.x;
    int ks = blockIdx.y;
    if (n >= N) return;
    int kchunk = K / KSPLIT;
    int k0 = ks * kchunk, k1 = k0 + kchunk;
    float acc[8];
#pragma unroll
    for (int r = 0; r < 8; r++) acc[r] = 0.0f;
    for (int k = k0; k < k1; k++) {
        float w = W[(size_t)k * N + n];
#pragma unroll
        for (int r = 0; r < 8; r++) acc[r] = fmaf(__ldg(&X[r * K + k]), w, acc[r]);
    }
#pragma unroll
    for (int r = 0; r < 8; r++) g_part[(ks * 8 + r) * N + n] = acc[r];
}
__global__ void sg_combine(const float* __restrict__ bias, float* __restrict__ Y,
                           int N, int act)
{
    int i = blockIdx.x * blockDim.x + threadIdx.x;
    if (i >= 8 * N) return;
    int r = i / N, n = i - r * N;
    float s = bias[n];
#pragma unroll
    for (int ks = 0; ks < KSPLIT; ks++) s += g_part[(ks * 8 + r) * N + n];
    Y[i] = apply_act(s, act);
}

// ---------------- entity similarities ----------------
__global__ __launch_bounds__(128) void sims_kernel(
    const float* __restrict__ E, const float* __restrict__ relf,
    float* __restrict__ sims)
{
    int n = blockIdx.x;
    int tid = threadIdx.x;
    __shared__ float rs[BATCH * Hd];
    for (int i = tid; i < BATCH * Hd; i += 128) rs[i] = relf[i];
    __syncthreads();
    float acc[8];
#pragma unroll
    for (int r = 0; r < 8; r++) acc[r] = 0.0f;
    for (int k = tid; k < Hd; k += 128) {
        float e = E[(size_t)n * Hd + k];
#pragma unroll
        for (int r = 0; r < 8; r++) acc[r] = fmaf(e, rs[r * Hd + k], acc[r]);
    }
    __shared__ float red[8][128];
#pragma unroll
    for (int r = 0; r < 8; r++) red[r][tid] = acc[r];
    __syncthreads();
    for (int o = 64; o; o >>= 1) {
        if (tid < o) {
#pragma unroll
            for (int r = 0; r < 8; r++) red[r][tid] += red[r][tid + o];
        }
        __syncthreads();
    }
    if (tid < 8) sims[tid * NENT + n] = red[tid][0];
}

// ---------------- top-5 (desc, lowest index on ties) ----------------
__global__ __launch_bounds__(256) void topk_kernel(const float* __restrict__ sims,
                                                   float* __restrict__ fidx_out)
{
    int b = blockIdx.x;
    int tid = threadIdx.x;
    __shared__ float sv[1024];
    for (int i = tid; i < 1024; i += 256)
        sv[i] = (i < NENT) ? sims[b * NENT + i] : NEG_INF;
    __syncthreads();
    __shared__ float bv[256];
    __shared__ int bi[256];
    for (int t = 0; t < TOPK; t++) {
        float best = NEG_INF; int besti = 0;
        for (int i = tid; i < NENT; i += 256) {
            float vv = sv[i];
            if (vv > best) { best = vv; besti = i; }
        }
        bv[tid] = best; bi[tid] = besti;
        __syncthreads();
        for (int o = 128; o; o >>= 1) {
            if (tid < o) {
                if (bv[tid + o] > bv[tid] ||
                    (bv[tid + o] == bv[tid] && bi[tid + o] < bi[tid])) {
                    bv[tid] = bv[tid + o]; bi[tid] = bi[tid + o];
                }
            }
            __syncthreads();
        }
        if (tid == 0) {
            g_topidx[b * TOPK + t] = bi[0];
            fidx_out[b * TOPK + t] = (float)bi[0];
            sv[bi[0]] = NEG_INF;
        }
        __syncthreads();
    }
}

// ---------------- gather retrieved entities + build reasoning input ----------------
__global__ __launch_bounds__(256) void build_rin(
    const float* __restrict__ E, const float* __restrict__ relf,
    float* __restrict__ ret_out)
{
    int b = blockIdx.x;
    for (int h = threadIdx.x; h < Hd; h += 256) {
        float s = 0.0f;
#pragma unroll
        for (int k = 0; k < TOPK; k++) {
            float v = E[(size_t)g_topidx[b * TOPK + k] * Hd + h];
            ret_out[((size_t)b * TOPK + k) * Hd + h] = v;
            s += v;
        }
        g_rin[b * 3 * Hd + h]          = s * (1.0f / TOPK);
        g_rin[b * 3 * Hd + Hd + h]     = relf[b * Hd + h];
        g_rin[b * 3 * Hd + 2 * Hd + h] = g_pooled[b * Hd + h];
    }
}

// ---------------- launch ----------------
extern "C" void kernel_launch(void* const* d_in, const int* in_sizes, int n_in,
                              void* d_out, int out_size)
{
    const float* hid    = (const float*)d_in[0];
    const float* ent    = (const float*)d_in[1];
    const float* ee_w1  = (const float*)d_in[2];
    const float* ee_b1  = (const float*)d_in[3];
    const float* ee_w2  = (const float*)d_in[4];
    const float* ee_b2  = (const float*)d_in[5];
    const float* ee_g   = (const float*)d_in[6];
    const float* ee_be  = (const float*)d_in[7];
    const float* re_w1  = (const float*)d_in[8];
    const float* re_b1  = (const float*)d_in[9];
    const float* re_w2  = (const float*)d_in[10];
    const float* re_b2  = (const float*)d_in[11];
    const float* re_g   = (const float*)d_in[12];
    const float* re_be  = (const float*)d_in[13];
    const float* rn_w1  = (const float*)d_in[14];
    const float* rn_b1  = (const float*)d_in[15];
    const float* rn_w2  = (const float*)d_in[16];
    const float* rn_b2  = (const float*)d_in[17];
    const float* rn_g   = (const float*)d_in[18];
    const float* rn_be  = (const float*)d_in[19];
    const float* vn_w1  = (const float*)d_in[20];
    const float* vn_b1  = (const float*)d_in[21];
    const float* vn_w2  = (const float*)d_in[22];
    const float* vn_b2  = (const float*)d_in[23];
    float* out = (float*)d_out;

    __half *ah, *mh, *wt1, *wt2;
    float *pooled, *rmid, *rraw, *rin, *rmid2, *vmid;
    cudaGetSymbolAddress((void**)&ah,  g_ah);
    cudaGetSymbolAddress((void**)&mh,  g_mh);
    cudaGetSymbolAddress((void**)&wt1, g_wt1);
    cudaGetSymbolAddress((void**)&wt2, g_wt2);
    cudaGetSymbolAddress((void**)&pooled, g_pooled);
    cudaGetSymbolAddress((void**)&rmid,   g_rmid);
    cudaGetSymbolAddress((void**)&rraw,   g_rraw);
    cudaGetSymbolAddress((void**)&rin,    g_rin);
    cudaGetSymbolAddress((void**)&rmid2,  g_rmid2);
    cudaGetSymbolAddress((void**)&vmid,   g_vmid);

    cudaFuncSetAttribute(gemm_tc<Hd, 2*Hd>,
                         cudaFuncAttributeMaxDynamicSharedMemorySize, GSMEM);
    cudaFuncSetAttribute(gemm_tc<2*Hd, Hd>,
                         cudaFuncAttributeMaxDynamicSharedMemorySize, GSMEM);

    // one-time host resources (no device memory involved)
    static cudaStream_t s2 = nullptr, s3 = nullptr, s4 = nullptr;
    static cudaEvent_t evFork = nullptr, evPrep = nullptr;
    static cudaEvent_t evJoinB = nullptr, evJoin3 = nullptr, evJoin4 = nullptr;
    if (!s2) {
        cudaStreamCreateWithFlags(&s2, cudaStreamNonBlocking);
        cudaStreamCreateWithFlags(&s3, cudaStreamNonBlocking);
        cudaStreamCreateWithFlags(&s4, cudaStreamNonBlocking);
        cudaEventCreateWithFlags(&evFork, cudaEventDisableTiming);
        cudaEventCreateWithFlags(&evPrep, cudaEventDisableTiming);
        cudaEventCreateWithFlags(&evJoinB, cudaEventDisableTiming);
        cudaEventCreateWithFlags(&evJoin3, cudaEventDisableTiming);
        cudaEventCreateWithFlags(&evJoin4, cudaEventDisableTiming);
    }

    const int NSLAB = 8;
    const int MS = MTOK / NSLAB;   // 2048 rows per slab

    // ---- fork: side streams join the capture ----
    cudaEventRecord(evFork, 0);
    cudaStreamWaitEvent(s2, evFork, 0);

    // ================= Chain B (stream s2): pooled path =========================
    pool_partial<<<dim3(32, PSEG), 256, 0, s2>>>(hid);
    pool_combine<<<32, 256, 0, s2>>>();
    sg_partial<<<dim3(Hd / 256, KSPLIT), 256, 0, s2>>>(pooled, re_w1, Hd, Hd);
    sg_combine<<<(8 * Hd + 255) / 256, 256, 0, s2>>>(re_b1, rmid, Hd, 1);
    sg_partial<<<dim3(Hd / 256, KSPLIT), 256, 0, s2>>>(rmid, re_w2, Hd, Hd);
    sg_combine<<<(8 * Hd + 255) / 256, 256, 0, s2>>>(re_b2, rraw, Hd, 0);
    ln_rows<<<BATCH, 256, 0, s2>>>(rraw, re_g, re_be, out + RF_OFF);
    sims_kernel<<<NENT, 128, 0, s2>>>(ent, out + RF_OFF, out + SIM_OFF);
    topk_kernel<<<BATCH, 256, 0, s2>>>(out + SIM_OFF, out + IDX_OFF);
    build_rin<<<BATCH, 256, 0, s2>>>(ent, out + RF_OFF, out + RET_OFF);
    sg_partial<<<dim3(2 * Hd / 256, KSPLIT), 256, 0, s2>>>(rin, rn_w1, 3 * Hd, 2 * Hd);
    sg_combine<<<(8 * 2 * Hd + 255) / 256, 256, 0, s2>>>(rn_b1, rmid2, 2 * Hd, 1);
    sg_partial<<<dim3(Hd / 256, KSPLIT), 256, 0, s2>>>(rmid2, rn_w2, 2 * Hd, Hd);
    sg_combine<<<(8 * Hd + 255) / 256, 256, 0, s2>>>(rn_b2, rraw, Hd, 0);
    ln_rows<<<BATCH, 256, 0, s2>>>(rraw, rn_g, rn_be, out + RO_OFF);
    sg_partial<<<dim3(512 / 256, KSPLIT), 256, 0, s2>>>(out + RO_OFF, vn_w1, Hd, 512);
    sg_combine<<<(8 * 512 + 255) / 256, 256, 0, s2>>>(vn_b1, vmid, 512, 1);
    sg_partial<<<dim3(1, KSPLIT), 256, 0, s2>>>(vmid, vn_w2, 512, 1);
    sg_combine<<<1, 256, 0, s2>>>(vn_b2, out + VS_OFF, 1, 2);

    // ================= Chain A prep (default stream) ============================
    transpose_h16<<<dim3(2 * Hd / 32, Hd / 32), 256>>>(ee_w1, wt1, Hd, 2 * Hd);
    transpose_h16<<<dim3(Hd / 32, 2 * Hd / 32), 256>>>(ee_w2, wt2, 2 * Hd, Hd);
    cudaEventRecord(evPrep, 0);            // weights ready
    cudaStreamWaitEvent(s3, evPrep, 0);
    cudaStreamWaitEvent(s4, evPrep, 0);

    // ---- 8 slab-chains, round-robin over streams 0 / s3 / s4 ----
    for (int s = 0; s < NSLAB; s++) {
        cudaStream_t st = (s % 3 == 0) ? (cudaStream_t)0
                        : (s % 3 == 1) ? s3 : s4;
        int row0 = s * MS;
        convert_h16<<<(MS * Hd / 4 + 255) / 256, 256, 0, st>>>(
            hid + (size_t)row0 * Hd, ah + (size_t)row0 * Hd, MS * Hd / 4);
        gemm_tc<Hd, 2*Hd><<<dim3(2 * Hd / 128, MS / 128), 256, GSMEM, st>>>(
            ah, wt1, ee_b1, nullptr, mh, row0, 1);
        gemm_tc<2*Hd, Hd><<<dim3(Hd / 128, MS / 128), 256, GSMEM, st>>>(
            mh, wt2, ee_b2, out + EF_OFF, nullptr, row0, 0);
        ln_rows<<<MS, 256, 0, st>>>(out + EF_OFF + (size_t)row0 * Hd, ee_g, ee_be,
                                    out + EF_OFF + (size_t)row0 * Hd);
    }

    // ---- join: default stream waits for all side streams ----
    cudaEventRecord(evJoinB, s2);
    cudaStreamWaitEvent(0, evJoinB, 0);
    cudaEventRecord(evJoin3, s3);
    cudaStreamWaitEvent(0, evJoin3, 0);
    cudaEventRecord(evJoin4, s4);
    cudaStreamWaitEvent(0, evJoin4, 0);
}